// round 17
// baseline (speedup 1.0000x reference)
#include <cuda_runtime.h>
#include <cuda_fp16.h>

// Cubic B-spline prefilter (Unser), DCT-II mirror boundaries.
// kWH: W axis via the EXACT causal/anticausal IIR (pole p = sqrt(3)-2,
//      12-step warm-up, scalar register state only); H axis via the proven
//      13-tap KR6 FIR. Output staged fp16 in g_mid.
// kD : D axis 13-tap FIR, fp16 -> f32, occ 6 (R15, unchanged).

#define NAX   192
#define KR    6
#define NT    (2*KR + 1)        // 13 taps (H and D)
#define HALO2 12                // IIR warm-up length (W axis)
#define TW    32                // strip output width
#define LC    (TW + 2*HALO2)    // 56 loaded cols
#define P1    57                // smem pitch (odd -> conflict-free both ways)
#define SEGH  16                // H-phase outputs/thread
#define WLH   (SEGH + 2*KR)     // 28
#define SEGD  24
#define WLD   (SEGD + 2*KR)     // 36
#define TPBF  192
#define TPBD  256
#define VOL   (NAX * NAX * NAX)
#define NCH   8                 // 4 batch * 2 channel

#define PZ      (-0.26794919243112270647f)  // p = sqrt(3) - 2
#define INV1MP  (0.78867513459481287f)      // 1 / (1 - p)
#define PDIV    (0.21132486540518713f)      // p / (p - 1)

// fp16 staging buffer for the W+H intermediate (113 MB; legal scratch)
__device__ __half g_mid[(size_t)NCH * VOL];

// taps T[k] = sqrt(3)*p^|k-6| -> FFMA-imm in SASS (rt=1)
#define DECL_TAPS const float T[NT] = { \
     6.4102556e-04f, -2.3923386e-03f,  8.9283341e-03f, -3.3320997e-02f, \
     1.2435565e-01f, -4.6410161e-01f,  1.7320508e+00f, -4.6410161e-01f, \
     1.2435565e-01f, -3.3320997e-02f,  8.9283341e-03f, -2.3923386e-03f, \
     6.4102556e-04f }

__device__ __forceinline__ int mirror_idx(int i) {
    i = (i < 0) ? (-1 - i) : i;                  // half-sample left reflect
    return (i >= NAX) ? (2 * NAX - 1 - i) : i;   // half-sample right reflect
}

// ---------------------------------------------------------------------------
// Fused W+H pass, one 192 x 32 strip per block, one 192x57 smem buffer.
// Phase 1: load 192x56 (w-halo 12, mirrored), coalesced independent LDG.
// Phase 2: W axis IIR in place (thread = row; scalar u,v state only).
// Phase 3: H axis 13-tap FIR on cols [12,44), fp16 coalesced STG to g_mid.
// ---------------------------------------------------------------------------
__global__ __launch_bounds__(TPBF, 5) void kWH(const float* __restrict__ in) {
    extern __shared__ float s[];   // [192][P1]

    const int tid   = threadIdx.x;              // 0..191
    const int strip = blockIdx.x % (NAX / TW);  // 6 strips; adjacent -> L2 halo reuse
    const int slice = blockIdx.x / (NAX / TW);
    const int base  = slice * (NAX * NAX);
    const int wbase = strip * TW;

    // ---- load 192 x 56 (coalesced LDG, independent -> high MLP)
#pragma unroll
    for (int k = 0; k < (NAX * LC) / TPBF; ++k) {   // 56 iterations
        int i   = tid + TPBF * k;
        int row = i / LC;
        int c   = i - row * LC;
        s[row * P1 + c] = in[base + row * NAX + mirror_idx(wbase - HALO2 + c)];
    }
    __syncthreads();

    // ==== W axis IIR: thread owns row `tid` (private smem span, no races)
    {
        float* rp = &s[tid * P1];   // stride-57 -> conflict-free
        // causal u[i] = x[i] + p*u[i-1], steady-state init + 12-step warm-up
        float u = rp[0] * INV1MP;
#pragma unroll
        for (int i = 1; i < HALO2; ++i) u = fmaf(PZ, u, rp[i]);
#pragma unroll
        for (int i = HALO2; i < LC; ++i) { u = fmaf(PZ, u, rp[i]); rp[i] = u; }

        // anticausal v[i] = p*(v[i+1] - u[i]); write 6*v in place
        float v;
        if (strip == (NAX / TW - 1)) {
            v = rp[HALO2 + TW - 1] * PDIV;       // exact boundary init at x=191
            rp[HALO2 + TW - 1] = 6.0f * v;
        } else {
            v = rp[LC - 1] * PDIV;               // steady-state init + warm-up
#pragma unroll
            for (int i = LC - 2; i >= HALO2 + TW; --i) v = PZ * (v - rp[i]);
            v = PZ * (v - rp[HALO2 + TW - 1]);
            rp[HALO2 + TW - 1] = 6.0f * v;
        }
#pragma unroll
        for (int i = HALO2 + TW - 2; i >= HALO2; --i) {
            v = PZ * (v - rp[i]);
            rp[i] = 6.0f * v;
        }
    }
    __syncthreads();

    // ==== H axis FIR: 384 tasks = (w 0..31) x (hseg 0..11 of 16 outputs)
    DECL_TAPS;
#pragma unroll
    for (int r = 0; r < 2; ++r) {
        const int t    = tid + TPBF * r;
        const int w    = t & (TW - 1);
        const int hseg = t >> 5;                 // 0..11
        const int h0   = hseg * SEGH;

        float win[WLH];
#pragma unroll
        for (int m = 0; m < WLH; ++m)
            win[m] = s[mirror_idx(h0 - KR + m) * P1 + HALO2 + w];  // lane = w -> conflict-free

        __half* o = g_mid + base + wbase + w;
#pragma unroll
        for (int j = 0; j < SEGH; ++j) {
            float acc = 0.0f;
#pragma unroll
            for (int k = 0; k < NT; ++k) acc = fmaf(T[k], win[j + k], acc);
            o[(h0 + j) * NAX] = __float2half_rn(acc);   // 64B coalesced per j
        }
    }
}

// ---------------------------------------------------------------------------
// D pass (stride 192*192): g_mid (fp16) -> out (f32). Tile: 192(d) x 32(w).
// Occupancy 6 (regs 40 <= cap 42).  (R15, unchanged)
// ---------------------------------------------------------------------------
__global__ __launch_bounds__(TPBD, 6) void kD(float* __restrict__ out) {
    __shared__ float s[NAX][32];
    const int tid = threadIdx.x;
    const int c   = blockIdx.x % (NAX / 32);
    const int tt  = blockIdx.x / (NAX / 32);
    const int b   = tt / NAX;
    const int hh  = tt % NAX;
    const int base = b * VOL + hh * NAX + c * 32;

    const int w  = tid & 31;
    const int a4 = tid >> 5;
    const __half* src = g_mid + base + w;
#pragma unroll
    for (int k = 0; k < NAX / 8; ++k)   // 24 outstanding LDG.16/thread
        s[a4 + 8 * k][w] = __half2float(src[(a4 + 8 * k) * (NAX * NAX)]);
    __syncthreads();

    DECL_TAPS;
    const int a0 = (tid >> 5) * SEGD;
    float win[WLD];
#pragma unroll
    for (int m = 0; m < WLD; ++m)
        win[m] = s[mirror_idx(a0 - KR + m)][w];

#pragma unroll
    for (int j = 0; j < SEGD; ++j) {
        float acc = 0.0f;
#pragma unroll
        for (int k = 0; k < NT; ++k) acc = fmaf(T[k], win[j + k], acc);
        out[base + (a0 + j) * (NAX * NAX) + w] = acc;     // 128B coalesced per j
    }
}

extern "C" void kernel_launch(void* const* d_in, const int* in_sizes, int n_in,
                              void* d_out, int out_size) {
    const float* x = (const float*)d_in[0];
    float* y = (float*)d_out;

    const int smemWH = NAX * P1 * (int)sizeof(float);   // 43776 B

    static int attr_set = 0;
    if (!attr_set) {
        cudaFuncSetAttribute(kWH, cudaFuncAttributeMaxDynamicSharedMemorySize, smemWH);
        attr_set = 1;
    }

    const int gridWH = NCH * NAX * (NAX / TW);   // 9216 blocks
    const int gridD  = NCH * NAX * (NAX / 32);   // 9216 blocks

    kWH<<<gridWH, TPBF, smemWH>>>(x);   // W IIR + H FIR: x -> g_mid (fp16)
    kD<<<gridD, TPBD>>>(y);             // D FIR: g_mid -> d_out (f32)
}